// round 1
// baseline (speedup 1.0000x reference)
#include <cuda_runtime.h>
#include <math.h>

// ---------------- problem constants ----------------
#define B_   2
#define C_   768
#define CC_  384
#define G_   12
#define HD_  64
#define H_   112
#define W_   112
#define HW_  12544
#define S2_  49
#define K2_  256
#define SCALE_ 0.125f   // hd^-0.5 = 1/8, folded into k

// ---------------- static device scratch ----------------
__device__ float g_ctxp[B_ * CC_ * S2_];          // pooled ctx  (b,c,s)
__device__ float g_k   [B_ * G_ * S2_ * HD_];     // k, pre-scaled, (bg, s, c)
__device__ float g_v   [B_ * G_ * K2_ * HD_];     // v           (bg, m, c)
__device__ float g_q   [B_ * HW_ * C_];           // q transposed (b, p, o)
__device__ float g_ao  [B_ * HW_ * C_];           // attn out    (b, p, c)

// ================= pool ctx to 7x7 (16x16 windows) =================
// one warp per output (b,c,s); 256 pixels each
__global__ void pool_ctx_kernel(const float* __restrict__ ctx) {
    int warp = (blockIdx.x * blockDim.x + threadIdx.x) >> 5;
    int lane = threadIdx.x & 31;
    if (warp >= B_ * CC_ * S2_) return;
    int s  = warp % S2_;
    int bc = warp / S2_;
    int si = s / 7, sj = s % 7;
    const float* base = ctx + (size_t)bc * HW_ + (si * 16) * W_ + sj * 16;
    float sum = 0.f;
    #pragma unroll
    for (int t = lane; t < 256; t += 32)
        sum += base[(t >> 4) * W_ + (t & 15)];
    #pragma unroll
    for (int o = 16; o; o >>= 1) sum += __shfl_xor_sync(0xffffffffu, sum, o);
    if (lane == 0) g_ctxp[warp] = sum * (1.f / 256.f);
}

// ================= pool x to 16x16 (7x7 windows) -> v =================
// one thread per output (b,cg,m)
__global__ void pool_v_kernel(const float* __restrict__ x) {
    int idx = blockIdx.x * blockDim.x + threadIdx.x;
    if (idx >= B_ * C_ * K2_) return;
    int m  = idx % K2_;
    int bc = idx / K2_;
    int b  = bc / C_;
    int cg = bc % C_;
    int mi = m >> 4, mj = m & 15;
    const float* base = x + (size_t)bc * HW_ + (mi * 7) * W_ + mj * 7;
    float sum = 0.f;
    #pragma unroll
    for (int r = 0; r < 7; r++)
        #pragma unroll
        for (int cc = 0; cc < 7; cc++)
            sum += base[r * W_ + cc];
    int g = cg >> 6, cl = cg & 63;
    g_v[(((size_t)(b * G_ + g)) * K2_ + m) * HD_ + cl] = sum * (1.f / 49.f);
}

// ================= k = scale * wk @ pooled_ctx =================
// (pool and 1x1 conv commute) — one block per (b,o), thread = s
__global__ void k_proj_kernel(const float* __restrict__ wk) {
    int bo = blockIdx.x;
    int b = bo / C_, o = bo % C_;
    int s = threadIdx.x;
    if (s >= S2_) return;
    const float* cp = g_ctxp + (size_t)b * CC_ * S2_ + s;
    const float* wr = wk + (size_t)o * CC_;
    float acc = 0.f;
    #pragma unroll 4
    for (int c = 0; c < CC_; c++) acc += wr[c] * cp[c * S2_];
    int g = o >> 6, lo = o & 63;
    g_k[(((size_t)(b * G_ + g)) * S2_ + s) * HD_ + lo] = acc * SCALE_;
}

// ================= SGEMM: qT[b,p,o] = sum_c x[b,c,p] * wq[o,c] =================
// 128x128x8 tiles, 256 threads, 8x8 micro-tile
__global__ __launch_bounds__(256) void sgemm_q_kernel(const float* __restrict__ x,
                                                      const float* __restrict__ wq) {
    __shared__ float As[8][128];   // [k][p]
    __shared__ float Bs[8][128];   // [k][o]
    int b  = blockIdx.z;
    int p0 = blockIdx.x * 128, o0 = blockIdx.y * 128;
    const float* A = x + (size_t)b * C_ * HW_;
    int tid = threadIdx.x;
    int tx = tid & 15, ty = tid >> 4;
    float acc[8][8] = {};
    int akk = tid >> 5,        ap4 = (tid & 31) * 4;  // A: 8 rows of 32 float4
    int boo = tid >> 1,        bkq = (tid & 1) * 4;   // B: 128 rows of 2 float4

    for (int k0 = 0; k0 < C_; k0 += 8) {
        float4 av = *(const float4*)(A + (size_t)(k0 + akk) * HW_ + p0 + ap4);
        *(float4*)&As[akk][ap4] = av;
        float4 bv = *(const float4*)(wq + (size_t)(o0 + boo) * C_ + k0 + bkq);
        Bs[bkq + 0][boo] = bv.x; Bs[bkq + 1][boo] = bv.y;
        Bs[bkq + 2][boo] = bv.z; Bs[bkq + 3][boo] = bv.w;
        __syncthreads();
        #pragma unroll
        for (int kk = 0; kk < 8; kk++) {
            float4 a0 = *(float4*)&As[kk][ty * 8];
            float4 a1 = *(float4*)&As[kk][ty * 8 + 4];
            float4 b0 = *(float4*)&Bs[kk][tx * 8];
            float4 b1 = *(float4*)&Bs[kk][tx * 8 + 4];
            float ar[8] = {a0.x,a0.y,a0.z,a0.w,a1.x,a1.y,a1.z,a1.w};
            float br[8] = {b0.x,b0.y,b0.z,b0.w,b1.x,b1.y,b1.z,b1.w};
            #pragma unroll
            for (int i = 0; i < 8; i++)
                #pragma unroll
                for (int j = 0; j < 8; j++)
                    acc[i][j] += ar[i] * br[j];
        }
        __syncthreads();
    }
    float* out = g_q + (size_t)b * HW_ * C_;
    #pragma unroll
    for (int i = 0; i < 8; i++) {
        float* row = out + (size_t)(p0 + ty * 8 + i) * C_ + o0 + tx * 8;
        *(float4*)(row)     = make_float4(acc[i][0], acc[i][1], acc[i][2], acc[i][3]);
        *(float4*)(row + 4) = make_float4(acc[i][4], acc[i][5], acc[i][6], acc[i][7]);
    }
}

// ================= SGEMM: out[b,o,p] = sum_c ao[b,p,c]*pw[o,c] + pb[o] + x[b,o,p] =================
__global__ __launch_bounds__(256) void sgemm_proj_kernel(const float* __restrict__ pw,
                                                         const float* __restrict__ pb,
                                                         const float* __restrict__ x,
                                                         float* __restrict__ out) {
    __shared__ float As[8][128];   // [c][p]
    __shared__ float Bs[8][128];   // [c][o]
    int b  = blockIdx.z;
    int p0 = blockIdx.x * 128, o0 = blockIdx.y * 128;
    const float* A = g_ao + (size_t)b * HW_ * C_;
    int tid = threadIdx.x;
    int tx = tid & 15, ty = tid >> 4;
    float acc[8][8] = {};
    int app = tid >> 1, acq = (tid & 1) * 4;
    int boo = tid >> 1, bkq = (tid & 1) * 4;

    for (int k0 = 0; k0 < C_; k0 += 8) {
        float4 av = *(const float4*)(A + (size_t)(p0 + app) * C_ + k0 + acq);
        As[acq + 0][app] = av.x; As[acq + 1][app] = av.y;
        As[acq + 2][app] = av.z; As[acq + 3][app] = av.w;
        float4 bv = *(const float4*)(pw + (size_t)(o0 + boo) * C_ + k0 + bkq);
        Bs[bkq + 0][boo] = bv.x; Bs[bkq + 1][boo] = bv.y;
        Bs[bkq + 2][boo] = bv.z; Bs[bkq + 3][boo] = bv.w;
        __syncthreads();
        #pragma unroll
        for (int kk = 0; kk < 8; kk++) {
            float4 ov0 = *(float4*)&Bs[kk][ty * 8];
            float4 ov1 = *(float4*)&Bs[kk][ty * 8 + 4];
            float4 pv0 = *(float4*)&As[kk][tx * 8];
            float4 pv1 = *(float4*)&As[kk][tx * 8 + 4];
            float orr[8] = {ov0.x,ov0.y,ov0.z,ov0.w,ov1.x,ov1.y,ov1.z,ov1.w};
            float prr[8] = {pv0.x,pv0.y,pv0.z,pv0.w,pv1.x,pv1.y,pv1.z,pv1.w};
            #pragma unroll
            for (int i = 0; i < 8; i++)
                #pragma unroll
                for (int j = 0; j < 8; j++)
                    acc[i][j] += orr[i] * prr[j];
        }
        __syncthreads();
    }
    #pragma unroll
    for (int i = 0; i < 8; i++) {
        int o = o0 + ty * 8 + i;
        float bias = pb[o];
        size_t off = ((size_t)(b * C_ + o)) * HW_ + p0 + tx * 8;
        float4 x0 = *(const float4*)(x + off);
        float4 x1 = *(const float4*)(x + off + 4);
        float4 r0 = make_float4(acc[i][0] + bias + x0.x, acc[i][1] + bias + x0.y,
                                acc[i][2] + bias + x0.z, acc[i][3] + bias + x0.w);
        float4 r1 = make_float4(acc[i][4] + bias + x1.x, acc[i][5] + bias + x1.y,
                                acc[i][6] + bias + x1.z, acc[i][7] + bias + x1.w);
        *(float4*)(out + off)     = r0;
        *(float4*)(out + off + 4) = r1;
    }
}

// ================= mega kernel: attn -> top32 mask -> S2->K2 -> softmax -> @V =================
// grid (49, 24): x = 256-row chunk, y = (b,g). 512 threads = 16 warps, 16 rows/warp,
// processed in groups of 4 to amortize smem reads of wd and v.
#define MEGA_KS_OFF   0            // 49*65 padded (3185) -> reserve 3200
#define MEGA_VS_OFF   3200         // 256*64 = 16384
#define MEGA_WD_OFF   19584        // 256*49 = 12544
#define MEGA_WARP_OFF 32128        // 16 warps * 1312 floats
#define MEGA_WARP_STRIDE 1312      // q 64 | sp 4*52=208 | om 4*256=1024
#define MEGA_SMEM_BYTES ((MEGA_WARP_OFF + 16 * MEGA_WARP_STRIDE) * 4)  // 212480

__global__ __launch_bounds__(512) void mega_kernel(const float* __restrict__ wd) {
    extern __shared__ float sm[];
    float* ks  = sm + MEGA_KS_OFF;
    float* vs  = sm + MEGA_VS_OFF;
    float* wds = sm + MEGA_WD_OFF;
    int tid = threadIdx.x, lane = tid & 31, w = tid >> 5;
    float* wsm = sm + MEGA_WARP_OFF + w * MEGA_WARP_STRIDE;
    float* qsm = wsm;          // 64
    float* sp  = wsm + 64;     // 4 rows * 52
    float* om  = wsm + 272;    // 4 rows * 256

    int bg = blockIdx.y;
    int b = bg / G_, g = bg % G_;
    int chunk = blockIdx.x;

    // cooperative smem fill
    for (int i = tid; i < S2_ * HD_; i += 512)
        ks[(i >> 6) * 65 + (i & 63)] = g_k[(size_t)bg * S2_ * HD_ + i];
    for (int i = tid; i < K2_ * HD_; i += 512)
        vs[i] = g_v[(size_t)bg * K2_ * HD_ + i];
    for (int i = tid; i < K2_ * S2_; i += 512)
        wds[i] = wd[i];
    __syncthreads();

    const float* qb = g_q  + (size_t)b * HW_ * C_ + g * HD_;
    float*       ab = g_ao + (size_t)b * HW_ * C_ + g * HD_;
    int s1 = lane;
    int s2 = lane + 32;
    int s2a = (s2 < S2_) ? s2 : 0;   // clamped address, result masked

    for (int g4 = 0; g4 < 4; g4++) {
        int pbase = chunk * 256 + w * 16 + g4 * 4;

        // ---- per-row: attn + top-32 threshold -> sparse in smem ----
        for (int rr = 0; rr < 4; rr++) {
            int p = pbase + rr;
            qsm[lane]      = qb[(size_t)p * C_ + lane];
            qsm[lane + 32] = qb[(size_t)p * C_ + lane + 32];
            __syncwarp();
            float a1 = 0.f, a2 = 0.f;
            #pragma unroll 8
            for (int c = 0; c < HD_; c++) {
                float qv = qsm[c];
                a1 += qv * ks[s1  * 65 + c];
                a2 += qv * ks[s2a * 65 + c];
            }
            float* att = sp + rr * 52;
            att[s1] = a1;
            if (s2 < S2_) att[s2] = a2;
            __syncwarp();
            int c1 = 0, c2 = 0;
            #pragma unroll
            for (int j = 0; j < S2_; j++) {
                float v = att[j];
                c1 += (v > a1);
                c2 += (v > a2);
            }
            __syncwarp();
            if (c1 >= 32) att[s1] = 0.f;
            if (s2 < S2_ && c2 >= 32) att[s2] = 0.f;
            __syncwarp();
        }

        // ---- omega logits, 4 rows blocked: lane owns m = lane + 32t ----
        float lg[4][8];
        #pragma unroll
        for (int r = 0; r < 4; r++)
            #pragma unroll
            for (int t = 0; t < 8; t++) lg[r][t] = 0.f;
        for (int s = 0; s < S2_; s++) {
            float sv0 = sp[0 * 52 + s], sv1 = sp[1 * 52 + s];
            float sv2 = sp[2 * 52 + s], sv3 = sp[3 * 52 + s];
            #pragma unroll
            for (int t = 0; t < 8; t++) {
                float wv = wds[(lane + 32 * t) * S2_ + s];
                lg[0][t] += sv0 * wv;
                lg[1][t] += sv1 * wv;
                lg[2][t] += sv2 * wv;
                lg[3][t] += sv3 * wv;
            }
        }

        // ---- softmax per row, write normalized omega to smem ----
        #pragma unroll
        for (int r = 0; r < 4; r++) {
            float mx = lg[r][0];
            #pragma unroll
            for (int t = 1; t < 8; t++) mx = fmaxf(mx, lg[r][t]);
            #pragma unroll
            for (int o = 16; o; o >>= 1) mx = fmaxf(mx, __shfl_xor_sync(0xffffffffu, mx, o));
            float sum = 0.f;
            #pragma unroll
            for (int t = 0; t < 8; t++) { lg[r][t] = expf(lg[r][t] - mx); sum += lg[r][t]; }
            #pragma unroll
            for (int o = 16; o; o >>= 1) sum += __shfl_xor_sync(0xffffffffu, sum, o);
            float inv = 1.f / sum;
            #pragma unroll
            for (int t = 0; t < 8; t++) om[r * K2_ + lane + 32 * t] = lg[r][t] * inv;
        }
        __syncwarp();

        // ---- out = omega @ v, 4 rows blocked; lane owns channels (lane, lane+32) ----
        float accA[4] = {0.f, 0.f, 0.f, 0.f};
        float accB[4] = {0.f, 0.f, 0.f, 0.f};
        #pragma unroll 4
        for (int m = 0; m < K2_; m++) {
            float v1 = vs[m * HD_ + lane];
            float v2 = vs[m * HD_ + lane + 32];
            #pragma unroll
            for (int r = 0; r < 4; r++) {
                float wv = om[r * K2_ + m];
                accA[r] += wv * v1;
                accB[r] += wv * v2;
            }
        }
        #pragma unroll
        for (int r = 0; r < 4; r++) {
            int p = pbase + r;
            ab[(size_t)p * C_ + lane]      = accA[r];
            ab[(size_t)p * C_ + lane + 32] = accB[r];
        }
        __syncwarp();
    }
}

// ================= launch =================
extern "C" void kernel_launch(void* const* d_in, const int* in_sizes, int n_in,
                              void* d_out, int out_size) {
    const float* x   = (const float*)d_in[0];
    const float* ctx = (const float*)d_in[1];
    const float* wq  = (const float*)d_in[2];
    const float* wk  = (const float*)d_in[3];
    const float* wd  = (const float*)d_in[4];
    const float* pw  = (const float*)d_in[5];
    const float* pb  = (const float*)d_in[6];
    float* out = (float*)d_out;

    cudaFuncSetAttribute(mega_kernel, cudaFuncAttributeMaxDynamicSharedMemorySize,
                         MEGA_SMEM_BYTES);

    pool_ctx_kernel<<<(B_ * CC_ * S2_ + 7) / 8, 256>>>(ctx);         // 8 warps/block
    pool_v_kernel<<<(B_ * C_ * K2_ + 255) / 256, 256>>>(x);
    k_proj_kernel<<<B_ * C_, 64>>>(wk);
    sgemm_q_kernel<<<dim3(HW_ / 128, C_ / 128, B_), 256>>>(x, wq);
    mega_kernel<<<dim3(HW_ / 256, B_ * G_), 512, MEGA_SMEM_BYTES>>>(wd);
    sgemm_proj_kernel<<<dim3(HW_ / 128, C_ / 128, B_), 256>>>(pw, pb, x, out);
}

// round 4
// speedup vs baseline: 1.9421x; 1.9421x over previous
#include <cuda_runtime.h>
#include <cuda_bf16.h>
#include <cstdint>
#include <math.h>

// ---------------- problem constants ----------------
#define B_   2
#define C_   768
#define CC_  384
#define G_   12
#define HD_  64
#define H_   112
#define W_   112
#define HW_  12544
#define S2_  49
#define K2_  256
#define SCALE_ 0.125f   // hd^-0.5 = 1/8, folded into k

// ---------------- static device scratch ----------------
__device__ float g_ctxp[B_ * CC_ * S2_];          // pooled ctx  (b,c,s)
__device__ float g_k   [B_ * G_ * S2_ * HD_];     // k, pre-scaled, (bg, s, c)
__device__ float g_v   [B_ * G_ * K2_ * HD_];     // v           (bg, m, c)
__device__ float g_q   [B_ * HW_ * C_];           // q transposed (b, p, o) fp32
__device__ __nv_bfloat16 g_xb [B_ * C_ * HW_];    // x in bf16    (b, c, p)
__device__ __nv_bfloat16 g_wqb[C_ * C_];          // wq bf16      (o, c)
__device__ __nv_bfloat16 g_pwb[C_ * C_];          // proj_w bf16  (o, c)
__device__ __nv_bfloat16 g_aob[B_ * HW_ * C_];    // attn out bf16 (b, p, c)

// ================= fp32 -> bf16 conversions (write device globals directly) =================
__global__ void conv_x_kernel(const float4* __restrict__ src) {
    int i = blockIdx.x * blockDim.x + threadIdx.x;
    int n4 = (B_ * C_ * HW_) / 4;
    if (i >= n4) return;
    float4 v = src[i];
    __nv_bfloat162* dst = (__nv_bfloat162*)g_xb;
    dst[2 * i]     = __floats2bfloat162_rn(v.x, v.y);
    dst[2 * i + 1] = __floats2bfloat162_rn(v.z, v.w);
}

__global__ void conv_w_kernel(const float4* __restrict__ wq,
                              const float4* __restrict__ pw) {
    int i = blockIdx.x * blockDim.x + threadIdx.x;
    int n4 = (C_ * C_) / 4;
    if (i >= n4) return;
    float4 v = wq[i];
    __nv_bfloat162* dq = (__nv_bfloat162*)g_wqb;
    dq[2 * i]     = __floats2bfloat162_rn(v.x, v.y);
    dq[2 * i + 1] = __floats2bfloat162_rn(v.z, v.w);
    float4 u = pw[i];
    __nv_bfloat162* dp = (__nv_bfloat162*)g_pwb;
    dp[2 * i]     = __floats2bfloat162_rn(u.x, u.y);
    dp[2 * i + 1] = __floats2bfloat162_rn(u.z, u.w);
}

// ================= pool ctx to 7x7 (16x16 windows) =================
__global__ void pool_ctx_kernel(const float* __restrict__ ctx) {
    int warp = (blockIdx.x * blockDim.x + threadIdx.x) >> 5;
    int lane = threadIdx.x & 31;
    if (warp >= B_ * CC_ * S2_) return;
    int s  = warp % S2_;
    int bc = warp / S2_;
    int si = s / 7, sj = s % 7;
    const float* base = ctx + (size_t)bc * HW_ + (si * 16) * W_ + sj * 16;
    float sum = 0.f;
    #pragma unroll
    for (int t = lane; t < 256; t += 32)
        sum += base[(t >> 4) * W_ + (t & 15)];
    #pragma unroll
    for (int o = 16; o; o >>= 1) sum += __shfl_xor_sync(0xffffffffu, sum, o);
    if (lane == 0) g_ctxp[warp] = sum * (1.f / 256.f);
}

// ================= pool x to 16x16 (7x7 windows) -> v =================
__global__ void pool_v_kernel(const float* __restrict__ x) {
    int idx = blockIdx.x * blockDim.x + threadIdx.x;
    if (idx >= B_ * C_ * K2_) return;
    int m  = idx % K2_;
    int bc = idx / K2_;
    int b  = bc / C_;
    int cg = bc % C_;
    int mi = m >> 4, mj = m & 15;
    const float* base = x + (size_t)bc * HW_ + (mi * 7) * W_ + mj * 7;
    float sum = 0.f;
    #pragma unroll
    for (int r = 0; r < 7; r++)
        #pragma unroll
        for (int cc = 0; cc < 7; cc++)
            sum += base[r * W_ + cc];
    int g = cg >> 6, cl = cg & 63;
    g_v[(((size_t)(b * G_ + g)) * K2_ + m) * HD_ + cl] = sum * (1.f / 49.f);
}

// ================= k = scale * wk @ pooled_ctx =================
__global__ void k_proj_kernel(const float* __restrict__ wk) {
    int bo = blockIdx.x;
    int b = bo / C_, o = bo % C_;
    int s = threadIdx.x;
    if (s >= S2_) return;
    const float* cp = g_ctxp + (size_t)b * CC_ * S2_ + s;
    const float* wr = wk + (size_t)o * CC_;
    float acc = 0.f;
    #pragma unroll 4
    for (int c = 0; c < CC_; c++) acc += wr[c] * cp[c * S2_];
    int g = o >> 6, lo = o & 63;
    g_k[(((size_t)(b * G_ + g)) * S2_ + s) * HD_ + lo] = acc * SCALE_;
}

// ================= mma.sync helpers =================
__device__ __forceinline__ void ldsm_x4(uint32_t* r, uint32_t addr) {
    asm volatile("ldmatrix.sync.aligned.m8n8.x4.shared.b16 {%0,%1,%2,%3}, [%4];"
        : "=r"(r[0]), "=r"(r[1]), "=r"(r[2]), "=r"(r[3]) : "r"(addr));
}
__device__ __forceinline__ void ldsm_x4_t(uint32_t* r, uint32_t addr) {
    asm volatile("ldmatrix.sync.aligned.m8n8.x4.trans.shared.b16 {%0,%1,%2,%3}, [%4];"
        : "=r"(r[0]), "=r"(r[1]), "=r"(r[2]), "=r"(r[3]) : "r"(addr));
}
__device__ __forceinline__ void mma_bf16(float* c, const uint32_t* a,
                                         uint32_t b0, uint32_t b1) {
    asm volatile("mma.sync.aligned.m16n8k16.row.col.f32.bf16.bf16.f32 "
        "{%0,%1,%2,%3}, {%4,%5,%6,%7}, {%8,%9}, {%0,%1,%2,%3};"
        : "+f"(c[0]), "+f"(c[1]), "+f"(c[2]), "+f"(c[3])
        : "r"(a[0]), "r"(a[1]), "r"(a[2]), "r"(a[3]), "r"(b0), "r"(b1));
}

// A (q-GEMM) smem tile: [k=32][m=256] pad 264 (bf16)   -> ldmatrix trans
// A (proj)   smem tile: [m=256][k=32] pad 40           -> ldmatrix
// B          smem tile: [n=128][k=32] pad 40           -> ldmatrix
#define Q_ASZ (32 * 264)
#define P_ASZ (256 * 40)
#define MM_BSZ (128 * 40)
#define Q_SMEM_BYTES ((2 * Q_ASZ + 2 * MM_BSZ) * 2)
#define P_SMEM_BYTES ((2 * P_ASZ + 2 * MM_BSZ) * 2)

// ================= GEMM-q: g_q[b,p,o] = sum_c xb[b,c,p] * wqb[o,c] =================
__global__ __launch_bounds__(256) void mma_q_kernel() {
    extern __shared__ __align__(16) __nv_bfloat16 smq[];
    __nv_bfloat16* As = smq;                 // 2 x 32 x 264
    __nv_bfloat16* Bs = smq + 2 * Q_ASZ;     // 2 x 128 x 40

    int b  = blockIdx.z;
    int p0 = blockIdx.x * 256, o0 = blockIdx.y * 128;
    const __nv_bfloat16* A  = g_xb + (size_t)b * C_ * HW_;
    const __nv_bfloat16* Bm = g_wqb;

    int tid = threadIdx.x, lane = tid & 31, w = tid >> 5;
    int wm = (w & 3) * 64, wn = (w >> 2) * 64;

    int a_k = tid >> 5, a_m = (tid & 31) * 8;   // A tile: 4 passes of 8 k-rows
    int b_n = tid >> 2, b_k = (tid & 3) * 8;    // B tile: 2 passes of 64 n-rows

    uint32_t as_base = (uint32_t)__cvta_generic_to_shared(As);
    uint32_t bs_base = (uint32_t)__cvta_generic_to_shared(Bs);

    int lr = lane & 7, lg = lane >> 3;
    // A (trans): matrices (k0,m0)(k0,m8)(k8,m0)(k8,m8)
    int at_row = ((lg >> 1) << 3) + lr, at_col = (lg & 1) << 3;
    // B: matrices (n0,k0)(n0,k8)(n8,k0)(n8,k8)
    int bt_row = ((lg >> 1) << 3) + lr, bt_col = (lg & 1) << 3;

    float acc[4][8][4];
    #pragma unroll
    for (int i = 0; i < 4; i++)
        #pragma unroll
        for (int j = 0; j < 8; j++)
            #pragma unroll
            for (int t = 0; t < 4; t++) acc[i][j][t] = 0.f;

    // prologue: tile 0
    #pragma unroll
    for (int i = 0; i < 4; i++) {
        uint4 v = *(const uint4*)(A + (size_t)(a_k + i * 8) * HW_ + p0 + a_m);
        *(uint4*)(As + (a_k + i * 8) * 264 + a_m) = v;
    }
    #pragma unroll
    for (int i = 0; i < 2; i++) {
        uint4 v = *(const uint4*)(Bm + (size_t)(o0 + b_n + i * 64) * C_ + b_k);
        *(uint4*)(Bs + (b_n + i * 64) * 40 + b_k) = v;
    }
    __syncthreads();

    for (int kc = 0; kc < 24; kc++) {
        int cur = kc & 1, nxt = cur ^ 1;
        uint4 pa[4], pbv[2];
        if (kc < 23) {
            int kc0 = (kc + 1) * 32;
            #pragma unroll
            for (int i = 0; i < 4; i++)
                pa[i] = *(const uint4*)(A + (size_t)(kc0 + a_k + i * 8) * HW_ + p0 + a_m);
            #pragma unroll
            for (int i = 0; i < 2; i++)
                pbv[i] = *(const uint4*)(Bm + (size_t)(o0 + b_n + i * 64) * C_ + kc0 + b_k);
        }
        uint32_t asb = as_base + cur * (Q_ASZ * 2);
        uint32_t bsb = bs_base + cur * (MM_BSZ * 2);
        #pragma unroll
        for (int kk = 0; kk < 32; kk += 16) {
            uint32_t af[4][4], bf[4][4];
            #pragma unroll
            for (int i = 0; i < 4; i++)
                ldsm_x4_t(af[i], asb + ((kk + at_row) * 264 + wm + i * 16 + at_col) * 2);
            #pragma unroll
            for (int j2 = 0; j2 < 4; j2++)
                ldsm_x4(bf[j2], bsb + ((wn + j2 * 16 + bt_row) * 40 + kk + bt_col) * 2);
            #pragma unroll
            for (int i = 0; i < 4; i++)
                #pragma unroll
                for (int j = 0; j < 8; j++)
                    mma_bf16(acc[i][j], af[i], bf[j >> 1][(j & 1) * 2], bf[j >> 1][(j & 1) * 2 + 1]);
        }
        if (kc < 23) {
            #pragma unroll
            for (int i = 0; i < 4; i++)
                *(uint4*)(As + nxt * Q_ASZ + (a_k + i * 8) * 264 + a_m) = pa[i];
            #pragma unroll
            for (int i = 0; i < 2; i++)
                *(uint4*)(Bs + nxt * MM_BSZ + (b_n + i * 64) * 40 + b_k) = pbv[i];
            __syncthreads();
        }
    }

    float* outp = g_q + (size_t)b * HW_ * C_;
    int rr = lane >> 2, cc0 = (lane & 3) * 2;
    #pragma unroll
    for (int i = 0; i < 4; i++)
        #pragma unroll
        for (int j = 0; j < 8; j++) {
            int r0 = p0 + wm + i * 16 + rr;
            int cc = o0 + wn + j * 8 + cc0;
            *(float2*)&outp[(size_t)r0 * C_ + cc]       = make_float2(acc[i][j][0], acc[i][j][1]);
            *(float2*)&outp[(size_t)(r0 + 8) * C_ + cc] = make_float2(acc[i][j][2], acc[i][j][3]);
        }
}

// ================= GEMM-proj: out[b,o,p] = sum_c aob[b,p,c]*pwb[o,c] + pb[o] + x[b,o,p] =================
__global__ __launch_bounds__(256) void mma_proj_kernel(const float* __restrict__ pbias,
                                                       const float* __restrict__ x,
                                                       float* __restrict__ out) {
    extern __shared__ __align__(16) __nv_bfloat16 smp[];
    __nv_bfloat16* As = smp;                 // 2 x 256 x 40
    __nv_bfloat16* Bs = smp + 2 * P_ASZ;     // 2 x 128 x 40

    int b  = blockIdx.z;
    int p0 = blockIdx.x * 256, o0 = blockIdx.y * 128;
    const __nv_bfloat16* A  = g_aob + (size_t)b * HW_ * C_;
    const __nv_bfloat16* Bm = g_pwb;

    int tid = threadIdx.x, lane = tid & 31, w = tid >> 5;
    int wm = (w & 3) * 64, wn = (w >> 2) * 64;

    int a_m = tid >> 2, a_kq = (tid & 3) * 8;   // A: 4 passes of 64 m-rows
    int b_n = tid >> 2, b_k = (tid & 3) * 8;

    uint32_t as_base = (uint32_t)__cvta_generic_to_shared(As);
    uint32_t bs_base = (uint32_t)__cvta_generic_to_shared(Bs);

    int lr = lane & 7, lg = lane >> 3;
    // A (non-trans): matrices (m0,k0)(m8,k0)(m0,k8)(m8,k8)
    int an_row = ((lg & 1) << 3) + lr, an_col = (lg >> 1) << 3;
    int bt_row = ((lg >> 1) << 3) + lr, bt_col = (lg & 1) << 3;

    float acc[4][8][4];
    #pragma unroll
    for (int i = 0; i < 4; i++)
        #pragma unroll
        for (int j = 0; j < 8; j++)
            #pragma unroll
            for (int t = 0; t < 4; t++) acc[i][j][t] = 0.f;

    #pragma unroll
    for (int i = 0; i < 4; i++) {
        uint4 v = *(const uint4*)(A + (size_t)(p0 + a_m + i * 64) * C_ + a_kq);
        *(uint4*)(As + (a_m + i * 64) * 40 + a_kq) = v;
    }
    #pragma unroll
    for (int i = 0; i < 2; i++) {
        uint4 v = *(const uint4*)(Bm + (size_t)(o0 + b_n + i * 64) * C_ + b_k);
        *(uint4*)(Bs + (b_n + i * 64) * 40 + b_k) = v;
    }
    __syncthreads();

    for (int kc = 0; kc < 24; kc++) {
        int cur = kc & 1, nxt = cur ^ 1;
        uint4 pa[4], pbv[2];
        if (kc < 23) {
            int kc0 = (kc + 1) * 32;
            #pragma unroll
            for (int i = 0; i < 4; i++)
                pa[i] = *(const uint4*)(A + (size_t)(p0 + a_m + i * 64) * C_ + kc0 + a_kq);
            #pragma unroll
            for (int i = 0; i < 2; i++)
                pbv[i] = *(const uint4*)(Bm + (size_t)(o0 + b_n + i * 64) * C_ + kc0 + b_k);
        }
        uint32_t asb = as_base + cur * (P_ASZ * 2);
        uint32_t bsb = bs_base + cur * (MM_BSZ * 2);
        #pragma unroll
        for (int kk = 0; kk < 32; kk += 16) {
            uint32_t af[4][4], bf[4][4];
            #pragma unroll
            for (int i = 0; i < 4; i++)
                ldsm_x4(af[i], asb + ((wm + i * 16 + an_row) * 40 + kk + an_col) * 2);
            #pragma unroll
            for (int j2 = 0; j2 < 4; j2++)
                ldsm_x4(bf[j2], bsb + ((wn + j2 * 16 + bt_row) * 40 + kk + bt_col) * 2);
            #pragma unroll
            for (int i = 0; i < 4; i++)
                #pragma unroll
                for (int j = 0; j < 8; j++)
                    mma_bf16(acc[i][j], af[i], bf[j >> 1][(j & 1) * 2], bf[j >> 1][(j & 1) * 2 + 1]);
        }
        if (kc < 23) {
            #pragma unroll
            for (int i = 0; i < 4; i++)
                *(uint4*)(As + nxt * P_ASZ + (a_m + i * 64) * 40 + a_kq) = pa[i];
            #pragma unroll
            for (int i = 0; i < 2; i++)
                *(uint4*)(Bs + nxt * MM_BSZ + (b_n + i * 64) * 40 + b_k) = pbv[i];
            __syncthreads();
        }
    }

    int rr = lane >> 2, cc0 = (lane & 3) * 2;
    #pragma unroll
    for (int i = 0; i < 4; i++)
        #pragma unroll
        for (int j = 0; j < 8; j++) {
            int p = p0 + wm + i * 16 + rr;
            int o = o0 + wn + j * 8 + cc0;
            float b0 = pbias[o], b1 = pbias[o + 1];
            size_t base0 = ((size_t)(b * C_ + o)) * HW_;
            size_t base1 = base0 + HW_;
            out[base0 + p]     = acc[i][j][0] + b0 + x[base0 + p];
            out[base1 + p]     = acc[i][j][1] + b1 + x[base1 + p];
            out[base0 + p + 8] = acc[i][j][2] + b0 + x[base0 + p + 8];
            out[base1 + p + 8] = acc[i][j][3] + b1 + x[base1 + p + 8];
        }
}

// ================= mega kernel: attn -> top32 mask -> S2->K2 -> softmax -> @V =================
#define MEGA_KS_OFF   0            // 49*65 padded -> reserve 3200
#define MEGA_VS_OFF   3200         // 256*64 = 16384
#define MEGA_WD_OFF   19584        // 256*49 = 12544
#define MEGA_WARP_OFF 32128        // 16 warps * 1312 floats
#define MEGA_WARP_STRIDE 1312      // q 64 | sp 4*52=208 | om 4*256=1024
#define MEGA_SMEM_BYTES ((MEGA_WARP_OFF + 16 * MEGA_WARP_STRIDE) * 4)  // 212480

__global__ __launch_bounds__(512) void mega_kernel(const float* __restrict__ wd) {
    extern __shared__ float sm[];
    float* ks  = sm + MEGA_KS_OFF;
    float* vs  = sm + MEGA_VS_OFF;
    float* wds = sm + MEGA_WD_OFF;
    int tid = threadIdx.x, lane = tid & 31, w = tid >> 5;
    float* wsm = sm + MEGA_WARP_OFF + w * MEGA_WARP_STRIDE;
    float* qsm = wsm;          // 64
    float* sp  = wsm + 64;     // 4 rows * 52
    float* om  = wsm + 272;    // 4 rows * 256

    int bg = blockIdx.y;
    int b = bg / G_, g = bg % G_;
    int chunk = blockIdx.x;

    for (int i = tid; i < S2_ * HD_; i += 512)
        ks[(i >> 6) * 65 + (i & 63)] = g_k[(size_t)bg * S2_ * HD_ + i];
    for (int i = tid; i < K2_ * HD_; i += 512)
        vs[i] = g_v[(size_t)bg * K2_ * HD_ + i];
    for (int i = tid; i < K2_ * S2_; i += 512)
        wds[i] = wd[i];
    __syncthreads();

    const float* qb = g_q + (size_t)b * HW_ * C_ + g * HD_;
    __nv_bfloat16* ab = g_aob + (size_t)b * HW_ * C_ + g * HD_;
    int s1 = lane;
    int s2 = lane + 32;
    int s2a = (s2 < S2_) ? s2 : 0;

    for (int g4 = 0; g4 < 4; g4++) {
        int pbase = chunk * 256 + w * 16 + g4 * 4;

        for (int rr = 0; rr < 4; rr++) {
            int p = pbase + rr;
            qsm[lane]      = qb[(size_t)p * C_ + lane];
            qsm[lane + 32] = qb[(size_t)p * C_ + lane + 32];
            __syncwarp();
            float a1 = 0.f, a2 = 0.f;
            #pragma unroll 8
            for (int c = 0; c < HD_; c++) {
                float qv = qsm[c];
                a1 += qv * ks[s1  * 65 + c];
                a2 += qv * ks[s2a * 65 + c];
            }
            float* att = sp + rr * 52;
            att[s1] = a1;
            if (s2 < S2_) att[s2] = a2;
            __syncwarp();
            int c1 = 0, c2 = 0;
            #pragma unroll
            for (int j = 0; j < S2_; j++) {
                float v = att[j];
                c1 += (v > a1);
                c2 += (v > a2);
            }
            __syncwarp();
            if (c1 >= 32) att[s1] = 0.f;
            if (s2 < S2_ && c2 >= 32) att[s2] = 0.f;
            __syncwarp();
        }

        float lg[4][8];
        #pragma unroll
        for (int r = 0; r < 4; r++)
            #pragma unroll
            for (int t = 0; t < 8; t++) lg[r][t] = 0.f;
        for (int s = 0; s < S2_; s++) {
            float sv0 = sp[0 * 52 + s], sv1 = sp[1 * 52 + s];
            float sv2 = sp[2 * 52 + s], sv3 = sp[3 * 52 + s];
            #pragma unroll
            for (int t = 0; t < 8; t++) {
                float wv = wds[(lane + 32 * t) * S2_ + s];
                lg[0][t] += sv0 * wv;
                lg[1][t] += sv1 * wv;
                lg[2][t] += sv2 * wv;
                lg[3][t] += sv3 * wv;
            }
        }

        #pragma unroll
        for (int r = 0; r < 4; r++) {
            float mx = lg[r][0];
            #pragma unroll
            for (int t = 1; t < 8; t++) mx = fmaxf(mx, lg[r][t]);
            #pragma unroll
            for (int o = 16; o; o >>= 1) mx = fmaxf(mx, __shfl_xor_sync(0xffffffffu, mx, o));
            float sum = 0.f;
            #pragma unroll
            for (int t = 0; t < 8; t++) { lg[r][t] = expf(lg[r][t] - mx); sum += lg[r][t]; }
            #pragma unroll
            for (int o = 16; o; o >>= 1) sum += __shfl_xor_sync(0xffffffffu, sum, o);
            float inv = 1.f / sum;
            #pragma unroll
            for (int t = 0; t < 8; t++) om[r * K2_ + lane + 32 * t] = lg[r][t] * inv;
        }
        __syncwarp();

        float accA[4] = {0.f, 0.f, 0.f, 0.f};
        float accB[4] = {0.f, 0.f, 0.f, 0.f};
        #pragma unroll 4
        for (int m = 0; m < K2_; m++) {
            float v1 = vs[m * HD_ + lane];
            float v2 = vs[m * HD_ + lane + 32];
            #pragma unroll
            for (int r = 0; r < 4; r++) {
                float wv = om[r * K2_ + m];
                accA[r] += wv * v1;
                accB[r] += wv * v2;
            }
        }
        #pragma unroll
        for (int r = 0; r < 4; r++) {
            int p = pbase + r;
            ab[(size_t)p * C_ + lane]      = __float2bfloat16(accA[r]);
            ab[(size_t)p * C_ + lane + 32] = __float2bfloat16(accB[r]);
        }
        __syncwarp();
    }
}

// ================= launch =================
extern "C" void kernel_launch(void* const* d_in, const int* in_sizes, int n_in,
                              void* d_out, int out_size) {
    const float* x   = (const float*)d_in[0];
    const float* ctx = (const float*)d_in[1];
    const float* wq  = (const float*)d_in[2];
    const float* wk  = (const float*)d_in[3];
    const float* wd  = (const float*)d_in[4];
    const float* pw  = (const float*)d_in[5];
    const float* pb  = (const float*)d_in[6];
    float* out = (float*)d_out;

    cudaFuncSetAttribute(mega_kernel, cudaFuncAttributeMaxDynamicSharedMemorySize,
                         MEGA_SMEM_BYTES);
    cudaFuncSetAttribute(mma_q_kernel, cudaFuncAttributeMaxDynamicSharedMemorySize,
                         Q_SMEM_BYTES);
    cudaFuncSetAttribute(mma_proj_kernel, cudaFuncAttributeMaxDynamicSharedMemorySize,
                         P_SMEM_BYTES);

    int nx4 = (B_ * C_ * HW_) / 4;
    int nw4 = (C_ * C_) / 4;
    conv_x_kernel<<<(nx4 + 255) / 256, 256>>>((const float4*)x);
    conv_w_kernel<<<(nw4 + 255) / 256, 256>>>((const float4*)wq, (const float4*)pw);

    pool_ctx_kernel<<<(B_ * CC_ * S2_ + 7) / 8, 256>>>(ctx);
    pool_v_kernel<<<(B_ * C_ * K2_ + 255) / 256, 256>>>(x);
    k_proj_kernel<<<B_ * C_, 64>>>(wk);

    mma_q_kernel<<<dim3(HW_ / 256, C_ / 128, B_), 256, Q_SMEM_BYTES>>>();
    mega_kernel<<<dim3(HW_ / 256, B_ * G_), 512, MEGA_SMEM_BYTES>>>(wd);
    mma_proj_kernel<<<dim3(HW_ / 256, C_ / 128, B_), 256, P_SMEM_BYTES>>>(pb, x, out);
}

// round 5
// speedup vs baseline: 4.2024x; 2.1639x over previous
#include <cuda_runtime.h>
#include <cuda_bf16.h>
#include <cstdint>
#include <math.h>

// ---------------- problem constants ----------------
#define B_   2
#define C_   768
#define CC_  384
#define G_   12
#define HD_  64
#define H_   112
#define W_   112
#define HW_  12544
#define S2_  49
#define K2_  256
#define SCALE_ 0.125f   // hd^-0.5 = 1/8, folded into k

// ---------------- static device scratch ----------------
__device__ float g_ctxp[B_ * CC_ * S2_];          // pooled ctx  (b,c,s)
__device__ float g_k   [B_ * G_ * S2_ * HD_];     // k, pre-scaled, (bg, s, c)
__device__ float g_v   [B_ * G_ * K2_ * HD_];     // v           (bg, m, c)
__device__ __nv_bfloat16 g_qb [B_ * HW_ * C_];    // q bf16       (b, p, o)
__device__ __nv_bfloat16 g_xb [B_ * C_ * HW_];    // x in bf16    (b, c, p)
__device__ __nv_bfloat16 g_wqb[C_ * C_];          // wq bf16      (o, c)
__device__ __nv_bfloat16 g_pwb[C_ * C_];          // proj_w bf16  (o, c)
__device__ __nv_bfloat16 g_aob[B_ * HW_ * C_];    // attn out bf16 (b, p, c)

// ================= fp32 -> bf16 conversions =================
__global__ void conv_x_kernel(const float4* __restrict__ src) {
    int i = blockIdx.x * blockDim.x + threadIdx.x;
    int n4 = (B_ * C_ * HW_) / 4;
    if (i >= n4) return;
    float4 v = src[i];
    __nv_bfloat162* dst = (__nv_bfloat162*)g_xb;
    dst[2 * i]     = __floats2bfloat162_rn(v.x, v.y);
    dst[2 * i + 1] = __floats2bfloat162_rn(v.z, v.w);
}

__global__ void conv_w_kernel(const float4* __restrict__ wq,
                              const float4* __restrict__ pw) {
    int i = blockIdx.x * blockDim.x + threadIdx.x;
    int n4 = (C_ * C_) / 4;
    if (i >= n4) return;
    float4 v = wq[i];
    __nv_bfloat162* dq = (__nv_bfloat162*)g_wqb;
    dq[2 * i]     = __floats2bfloat162_rn(v.x, v.y);
    dq[2 * i + 1] = __floats2bfloat162_rn(v.z, v.w);
    float4 u = pw[i];
    __nv_bfloat162* dp = (__nv_bfloat162*)g_pwb;
    dp[2 * i]     = __floats2bfloat162_rn(u.x, u.y);
    dp[2 * i + 1] = __floats2bfloat162_rn(u.z, u.w);
}

// ================= pool ctx to 7x7 (16x16 windows) =================
__global__ void pool_ctx_kernel(const float* __restrict__ ctx) {
    int warp = (blockIdx.x * blockDim.x + threadIdx.x) >> 5;
    int lane = threadIdx.x & 31;
    if (warp >= B_ * CC_ * S2_) return;
    int s  = warp % S2_;
    int bc = warp / S2_;
    int si = s / 7, sj = s % 7;
    const float* base = ctx + (size_t)bc * HW_ + (si * 16) * W_ + sj * 16;
    float sum = 0.f;
    #pragma unroll
    for (int t = lane; t < 256; t += 32)
        sum += base[(t >> 4) * W_ + (t & 15)];
    #pragma unroll
    for (int o = 16; o; o >>= 1) sum += __shfl_xor_sync(0xffffffffu, sum, o);
    if (lane == 0) g_ctxp[warp] = sum * (1.f / 256.f);
}

// ================= pool x to 16x16 (7x7 windows) -> v =================
__global__ void pool_v_kernel(const float* __restrict__ x) {
    int idx = blockIdx.x * blockDim.x + threadIdx.x;
    if (idx >= B_ * C_ * K2_) return;
    int m  = idx % K2_;
    int bc = idx / K2_;
    int b  = bc / C_;
    int cg = bc % C_;
    int mi = m >> 4, mj = m & 15;
    const float* base = x + (size_t)bc * HW_ + (mi * 7) * W_ + mj * 7;
    float sum = 0.f;
    #pragma unroll
    for (int r = 0; r < 7; r++)
        #pragma unroll
        for (int cc = 0; cc < 7; cc++)
            sum += base[r * W_ + cc];
    int g = cg >> 6, cl = cg & 63;
    g_v[(((size_t)(b * G_ + g)) * K2_ + m) * HD_ + cl] = sum * (1.f / 49.f);
}

// ================= k = scale * wk @ pooled_ctx =================
__global__ void k_proj_kernel(const float* __restrict__ wk) {
    int bo = blockIdx.x;
    int b = bo / C_, o = bo % C_;
    int s = threadIdx.x;
    if (s >= S2_) return;
    const float* cp = g_ctxp + (size_t)b * CC_ * S2_ + s;
    const float* wr = wk + (size_t)o * CC_;
    float acc = 0.f;
    #pragma unroll 4
    for (int c = 0; c < CC_; c++) acc += wr[c] * cp[c * S2_];
    int g = o >> 6, lo = o & 63;
    g_k[(((size_t)(b * G_ + g)) * S2_ + s) * HD_ + lo] = acc * SCALE_;
}

// ================= mma.sync helpers =================
__device__ __forceinline__ void ldsm_x4(uint32_t* r, uint32_t addr) {
    asm volatile("ldmatrix.sync.aligned.m8n8.x4.shared.b16 {%0,%1,%2,%3}, [%4];"
        : "=r"(r[0]), "=r"(r[1]), "=r"(r[2]), "=r"(r[3]) : "r"(addr));
}
__device__ __forceinline__ void ldsm_x4_t(uint32_t* r, uint32_t addr) {
    asm volatile("ldmatrix.sync.aligned.m8n8.x4.trans.shared.b16 {%0,%1,%2,%3}, [%4];"
        : "=r"(r[0]), "=r"(r[1]), "=r"(r[2]), "=r"(r[3]) : "r"(addr));
}
__device__ __forceinline__ void mma_bf16(float* c, const uint32_t* a,
                                         uint32_t b0, uint32_t b1) {
    asm volatile("mma.sync.aligned.m16n8k16.row.col.f32.bf16.bf16.f32 "
        "{%0,%1,%2,%3}, {%4,%5,%6,%7}, {%8,%9}, {%0,%1,%2,%3};"
        : "+f"(c[0]), "+f"(c[1]), "+f"(c[2]), "+f"(c[3])
        : "r"(a[0]), "r"(a[1]), "r"(a[2]), "r"(a[3]), "r"(b0), "r"(b1));
}
__device__ __forceinline__ uint32_t packbf2(float x, float y) {
    __nv_bfloat162 t = __floats2bfloat162_rn(x, y);
    return *(uint32_t*)&t;
}

// A (q-GEMM) smem tile: [k=32][m=256] pad 264 (bf16)   -> ldmatrix trans
// A (proj)   smem tile: [m=256][k=32] pad 40           -> ldmatrix
// B          smem tile: [n=128][k=32] pad 40           -> ldmatrix
#define Q_ASZ (32 * 264)
#define P_ASZ (256 * 40)
#define MM_BSZ (128 * 40)
#define Q_SMEM_BYTES ((2 * Q_ASZ + 2 * MM_BSZ) * 2)
#define P_SMEM_BYTES ((2 * P_ASZ + 2 * MM_BSZ) * 2)

// ================= GEMM-q: g_qb[b,p,o] = sum_c xb[b,c,p] * wqb[o,c] (bf16 out) =================
__global__ __launch_bounds__(256) void mma_q_kernel() {
    extern __shared__ __align__(16) __nv_bfloat16 smq[];
    __nv_bfloat16* As = smq;                 // 2 x 32 x 264
    __nv_bfloat16* Bs = smq + 2 * Q_ASZ;     // 2 x 128 x 40

    int b  = blockIdx.z;
    int p0 = blockIdx.x * 256, o0 = blockIdx.y * 128;
    const __nv_bfloat16* A  = g_xb + (size_t)b * C_ * HW_;
    const __nv_bfloat16* Bm = g_wqb;

    int tid = threadIdx.x, lane = tid & 31, w = tid >> 5;
    int wm = (w & 3) * 64, wn = (w >> 2) * 64;

    int a_k = tid >> 5, a_m = (tid & 31) * 8;
    int b_n = tid >> 2, b_k = (tid & 3) * 8;

    uint32_t as_base = (uint32_t)__cvta_generic_to_shared(As);
    uint32_t bs_base = (uint32_t)__cvta_generic_to_shared(Bs);

    int lr = lane & 7, lg = lane >> 3;
    int at_row = ((lg >> 1) << 3) + lr, at_col = (lg & 1) << 3;
    int bt_row = ((lg >> 1) << 3) + lr, bt_col = (lg & 1) << 3;

    float acc[4][8][4];
    #pragma unroll
    for (int i = 0; i < 4; i++)
        #pragma unroll
        for (int j = 0; j < 8; j++)
            #pragma unroll
            for (int t = 0; t < 4; t++) acc[i][j][t] = 0.f;

    #pragma unroll
    for (int i = 0; i < 4; i++) {
        uint4 v = *(const uint4*)(A + (size_t)(a_k + i * 8) * HW_ + p0 + a_m);
        *(uint4*)(As + (a_k + i * 8) * 264 + a_m) = v;
    }
    #pragma unroll
    for (int i = 0; i < 2; i++) {
        uint4 v = *(const uint4*)(Bm + (size_t)(o0 + b_n + i * 64) * C_ + b_k);
        *(uint4*)(Bs + (b_n + i * 64) * 40 + b_k) = v;
    }
    __syncthreads();

    for (int kc = 0; kc < 24; kc++) {
        int cur = kc & 1, nxt = cur ^ 1;
        uint4 pa[4], pbv[2];
        if (kc < 23) {
            int kc0 = (kc + 1) * 32;
            #pragma unroll
            for (int i = 0; i < 4; i++)
                pa[i] = *(const uint4*)(A + (size_t)(kc0 + a_k + i * 8) * HW_ + p0 + a_m);
            #pragma unroll
            for (int i = 0; i < 2; i++)
                pbv[i] = *(const uint4*)(Bm + (size_t)(o0 + b_n + i * 64) * C_ + kc0 + b_k);
        }
        uint32_t asb = as_base + cur * (Q_ASZ * 2);
        uint32_t bsb = bs_base + cur * (MM_BSZ * 2);
        #pragma unroll
        for (int kk = 0; kk < 32; kk += 16) {
            uint32_t af[4][4], bf[4][4];
            #pragma unroll
            for (int i = 0; i < 4; i++)
                ldsm_x4_t(af[i], asb + ((kk + at_row) * 264 + wm + i * 16 + at_col) * 2);
            #pragma unroll
            for (int j2 = 0; j2 < 4; j2++)
                ldsm_x4(bf[j2], bsb + ((wn + j2 * 16 + bt_row) * 40 + kk + bt_col) * 2);
            #pragma unroll
            for (int i = 0; i < 4; i++)
                #pragma unroll
                for (int j = 0; j < 8; j++)
                    mma_bf16(acc[i][j], af[i], bf[j >> 1][(j & 1) * 2], bf[j >> 1][(j & 1) * 2 + 1]);
        }
        if (kc < 23) {
            #pragma unroll
            for (int i = 0; i < 4; i++)
                *(uint4*)(As + nxt * Q_ASZ + (a_k + i * 8) * 264 + a_m) = pa[i];
            #pragma unroll
            for (int i = 0; i < 2; i++)
                *(uint4*)(Bs + nxt * MM_BSZ + (b_n + i * 64) * 40 + b_k) = pbv[i];
            __syncthreads();
        }
    }

    __nv_bfloat16* outp = g_qb + (size_t)b * HW_ * C_;
    int rr = lane >> 2, cc0 = (lane & 3) * 2;
    #pragma unroll
    for (int i = 0; i < 4; i++)
        #pragma unroll
        for (int j = 0; j < 8; j++) {
            int r0 = p0 + wm + i * 16 + rr;
            int cc = o0 + wn + j * 8 + cc0;
            *(__nv_bfloat162*)(outp + (size_t)r0 * C_ + cc) =
                __floats2bfloat162_rn(acc[i][j][0], acc[i][j][1]);
            *(__nv_bfloat162*)(outp + (size_t)(r0 + 8) * C_ + cc) =
                __floats2bfloat162_rn(acc[i][j][2], acc[i][j][3]);
        }
}

// ================= GEMM-proj: out = aob @ pw^T + pb + x =================
__global__ __launch_bounds__(256) void mma_proj_kernel(const float* __restrict__ pbias,
                                                       const float* __restrict__ x,
                                                       float* __restrict__ out) {
    extern __shared__ __align__(16) __nv_bfloat16 smp[];
    __nv_bfloat16* As = smp;                 // 2 x 256 x 40
    __nv_bfloat16* Bs = smp + 2 * P_ASZ;     // 2 x 128 x 40

    int b  = blockIdx.z;
    int p0 = blockIdx.x * 256, o0 = blockIdx.y * 128;
    const __nv_bfloat16* A  = g_aob + (size_t)b * HW_ * C_;
    const __nv_bfloat16* Bm = g_pwb;

    int tid = threadIdx.x, lane = tid & 31, w = tid >> 5;
    int wm = (w & 3) * 64, wn = (w >> 2) * 64;

    int a_m = tid >> 2, a_kq = (tid & 3) * 8;
    int b_n = tid >> 2, b_k = (tid & 3) * 8;

    uint32_t as_base = (uint32_t)__cvta_generic_to_shared(As);
    uint32_t bs_base = (uint32_t)__cvta_generic_to_shared(Bs);

    int lr = lane & 7, lg = lane >> 3;
    int an_row = ((lg & 1) << 3) + lr, an_col = (lg >> 1) << 3;
    int bt_row = ((lg >> 1) << 3) + lr, bt_col = (lg & 1) << 3;

    float acc[4][8][4];
    #pragma unroll
    for (int i = 0; i < 4; i++)
        #pragma unroll
        for (int j = 0; j < 8; j++)
            #pragma unroll
            for (int t = 0; t < 4; t++) acc[i][j][t] = 0.f;

    #pragma unroll
    for (int i = 0; i < 4; i++) {
        uint4 v = *(const uint4*)(A + (size_t)(p0 + a_m + i * 64) * C_ + a_kq);
        *(uint4*)(As + (a_m + i * 64) * 40 + a_kq) = v;
    }
    #pragma unroll
    for (int i = 0; i < 2; i++) {
        uint4 v = *(const uint4*)(Bm + (size_t)(o0 + b_n + i * 64) * C_ + b_k);
        *(uint4*)(Bs + (b_n + i * 64) * 40 + b_k) = v;
    }
    __syncthreads();

    for (int kc = 0; kc < 24; kc++) {
        int cur = kc & 1, nxt = cur ^ 1;
        uint4 pa[4], pbv[2];
        if (kc < 23) {
            int kc0 = (kc + 1) * 32;
            #pragma unroll
            for (int i = 0; i < 4; i++)
                pa[i] = *(const uint4*)(A + (size_t)(p0 + a_m + i * 64) * C_ + kc0 + a_kq);
            #pragma unroll
            for (int i = 0; i < 2; i++)
                pbv[i] = *(const uint4*)(Bm + (size_t)(o0 + b_n + i * 64) * C_ + kc0 + b_k);
        }
        uint32_t asb = as_base + cur * (P_ASZ * 2);
        uint32_t bsb = bs_base + cur * (MM_BSZ * 2);
        #pragma unroll
        for (int kk = 0; kk < 32; kk += 16) {
            uint32_t af[4][4], bf[4][4];
            #pragma unroll
            for (int i = 0; i < 4; i++)
                ldsm_x4(af[i], asb + ((wm + i * 16 + an_row) * 40 + kk + an_col) * 2);
            #pragma unroll
            for (int j2 = 0; j2 < 4; j2++)
                ldsm_x4(bf[j2], bsb + ((wn + j2 * 16 + bt_row) * 40 + kk + bt_col) * 2);
            #pragma unroll
            for (int i = 0; i < 4; i++)
                #pragma unroll
                for (int j = 0; j < 8; j++)
                    mma_bf16(acc[i][j], af[i], bf[j >> 1][(j & 1) * 2], bf[j >> 1][(j & 1) * 2 + 1]);
        }
        if (kc < 23) {
            #pragma unroll
            for (int i = 0; i < 4; i++)
                *(uint4*)(As + nxt * P_ASZ + (a_m + i * 64) * 40 + a_kq) = pa[i];
            #pragma unroll
            for (int i = 0; i < 2; i++)
                *(uint4*)(Bs + nxt * MM_BSZ + (b_n + i * 64) * 40 + b_k) = pbv[i];
            __syncthreads();
        }
    }

    int rr = lane >> 2, cc0 = (lane & 3) * 2;
    #pragma unroll
    for (int i = 0; i < 4; i++)
        #pragma unroll
        for (int j = 0; j < 8; j++) {
            int p = p0 + wm + i * 16 + rr;
            int o = o0 + wn + j * 8 + cc0;
            float b0 = pbias[o], b1 = pbias[o + 1];
            size_t base0 = ((size_t)(b * C_ + o)) * HW_;
            size_t base1 = base0 + HW_;
            out[base0 + p]     = acc[i][j][0] + b0 + x[base0 + p];
            out[base1 + p]     = acc[i][j][1] + b1 + x[base1 + p];
            out[base0 + p + 8] = acc[i][j][2] + b0 + x[base0 + p + 8];
            out[base1 + p + 8] = acc[i][j][3] + b1 + x[base1 + p + 8];
        }
}

// ================= mega2: tensor-core attn -> top32 -> logits -> softmax -> @V =================
// smem (bytes): wd 256x72 bf16 @0 (36864) | v 256x72 bf16 @36864 | k 64x72 bf16 @73728 (9216)
//               per-warp @82944 + w*8192: q 16x72 bf16 (2304) | sparse 16x72 bf16 (2304) | att 16x52 f32 (3328)
#define MG_WD   0
#define MG_V    36864
#define MG_K    73728
#define MG_WB   82944
#define MG_SMEM (82944 + 16 * 8192)   // 214016

__global__ __launch_bounds__(512) void mega2_kernel(const float* __restrict__ wd) {
    extern __shared__ __align__(16) char smraw[];
    __nv_bfloat16* wds = (__nv_bfloat16*)(smraw + MG_WD);
    __nv_bfloat16* vs  = (__nv_bfloat16*)(smraw + MG_V);
    __nv_bfloat16* ks  = (__nv_bfloat16*)(smraw + MG_K);
    int tid = threadIdx.x, lane = tid & 31, w = tid >> 5;
    char* wb = smraw + MG_WB + w * 8192;
    __nv_bfloat16* qs = (__nv_bfloat16*)wb;
    __nv_bfloat16* sp = (__nv_bfloat16*)(wb + 2304);
    float* att = (float*)(wb + 4608);

    int bg = blockIdx.y;
    int b = bg / G_, g = bg % G_;
    __nv_bfloat16 zero = __float2bfloat16(0.f);

    // cooperative shared fills (bf16 convert, zero-pad)
    for (int i = tid; i < K2_ * 64; i += 512) {
        int r = i >> 6, c = i & 63;
        wds[r * 72 + c] = (c < S2_) ? __float2bfloat16(wd[r * S2_ + c]) : zero;
        vs[r * 72 + c]  = __float2bfloat16(g_v[(size_t)bg * K2_ * HD_ + i]);
    }
    for (int i = tid; i < 64 * 64; i += 512) {
        int r = i >> 6, c = i & 63;
        ks[r * 72 + c] = (r < S2_) ? __float2bfloat16(g_k[(size_t)bg * S2_ * HD_ + r * HD_ + c]) : zero;
    }
    __syncthreads();

    int pbase = blockIdx.x * 256 + w * 16;
    const __nv_bfloat16* qb = g_qb + (size_t)b * HW_ * C_ + g * HD_;

    // load 16 q rows into per-warp tile
    for (int i = lane; i < 128; i += 32) {
        int r = i >> 3, cq = (i & 7) * 8;
        *(uint4*)(qs + r * 72 + cq) = *(const uint4*)(qb + (size_t)(pbase + r) * C_ + cq);
    }
    __syncwarp();

    int lr = lane & 7, lg = lane >> 3;
    int fa_row = ((lg & 1) << 3) + lr, fa_col = (lg >> 1) << 3;  // A non-trans / v-trans
    int fb_row = ((lg >> 1) << 3) + lr, fb_col = (lg & 1) << 3;  // B non-trans
    uint32_t qs_b = (uint32_t)__cvta_generic_to_shared(qs);
    uint32_t sp_b = (uint32_t)__cvta_generic_to_shared(sp);
    uint32_t ks_b = (uint32_t)__cvta_generic_to_shared(ks);
    uint32_t wd_b = (uint32_t)__cvta_generic_to_shared(wds);
    uint32_t vs_b = (uint32_t)__cvta_generic_to_shared(vs);

    // ---- attn = q @ k^T (16 x 56, K=64) ----
    uint32_t aq[4][4];
    #pragma unroll
    for (int kt = 0; kt < 4; kt++)
        ldsm_x4(aq[kt], qs_b + (fa_row * 72 + kt * 16 + fa_col) * 2);
    float ac[8][4];
    #pragma unroll
    for (int j = 0; j < 8; j++)
        #pragma unroll
        for (int t = 0; t < 4; t++) ac[j][t] = 0.f;
    #pragma unroll
    for (int kt = 0; kt < 4; kt++)
        #pragma unroll
        for (int jp = 0; jp < 4; jp++) {
            uint32_t bk[4];
            ldsm_x4(bk, ks_b + ((jp * 16 + fb_row) * 72 + kt * 16 + fb_col) * 2);
            mma_bf16(ac[jp * 2],     aq[kt], bk[0], bk[1]);
            mma_bf16(ac[jp * 2 + 1], aq[kt], bk[2], bk[3]);
        }

    int r0 = lane >> 2, cc0 = (lane & 3) * 2;
    #pragma unroll
    for (int jn = 0; jn < 7; jn++) {
        int col = jn * 8 + cc0;
        if (col < 52) {
            att[r0 * 52 + col]       = ac[jn][0];
            att[(r0 + 8) * 52 + col] = ac[jn][2];
        }
        if (col + 1 < 52) {
            att[r0 * 52 + col + 1]       = ac[jn][1];
            att[(r0 + 8) * 52 + col + 1] = ac[jn][3];
        }
    }
    __syncwarp();

    // ---- top-32 threshold per row (count strictly-greater) ----
    int s1 = lane, s2 = lane + 32;
    for (int r = 0; r < 16; r++) {
        float a1 = att[r * 52 + s1];
        float a2 = (s2 < S2_) ? att[r * 52 + s2] : 0.f;
        int c1 = 0, c2 = 0;
        #pragma unroll
        for (int j = 0; j < S2_; j++) {
            float v = att[r * 52 + j];
            c1 += (v > a1);
            c2 += (v > a2);
        }
        __syncwarp();
        if (c1 >= 32) att[r * 52 + s1] = 0.f;
        if (s2 < S2_ && c2 >= 32) att[r * 52 + s2] = 0.f;
        __syncwarp();
    }

    // ---- stage sparse as bf16 16x64 (zero-padded) ----
    for (int i = lane; i < 256; i += 32) {
        int r = i >> 4, c = 48 + (i & 15);
        sp[r * 72 + c] = zero;
    }
    __syncwarp();
    for (int r = 0; r < 16; r++) {
        sp[r * 72 + s1] = __float2bfloat16(att[r * 52 + s1]);
        if (s2 < S2_) sp[r * 72 + s2] = __float2bfloat16(att[r * 52 + s2]);
    }
    __syncwarp();

    uint32_t asp[4][4];
    #pragma unroll
    for (int kt = 0; kt < 4; kt++)
        ldsm_x4(asp[kt], sp_b + (fa_row * 72 + kt * 16 + fa_col) * 2);

    // ---- chunked: logits -> exp -> (omega in regs) @ V ----
    float acc[8][4];
    #pragma unroll
    for (int j = 0; j < 8; j++)
        #pragma unroll
        for (int t = 0; t < 4; t++) acc[j][t] = 0.f;
    float sumA = 0.f, sumB = 0.f;

    for (int cc = 0; cc < 8; cc++) {
        float lgc[4][4];
        #pragma unroll
        for (int t = 0; t < 4; t++)
            #pragma unroll
            for (int u = 0; u < 4; u++) lgc[t][u] = 0.f;
        #pragma unroll
        for (int kt = 0; kt < 4; kt++)
            #pragma unroll
            for (int jp = 0; jp < 2; jp++) {
                uint32_t bw[4];
                ldsm_x4(bw, wd_b + ((cc * 32 + jp * 16 + fb_row) * 72 + kt * 16 + fb_col) * 2);
                mma_bf16(lgc[jp * 2],     asp[kt], bw[0], bw[1]);
                mma_bf16(lgc[jp * 2 + 1], asp[kt], bw[2], bw[3]);
            }
        // exp (logits are tiny — no max subtraction needed) + row sums
        #pragma unroll
        for (int t = 0; t < 4; t++) {
            #pragma unroll
            for (int u = 0; u < 4; u++) lgc[t][u] = __expf(lgc[t][u]);
            sumA += lgc[t][0] + lgc[t][1];
            sumB += lgc[t][2] + lgc[t][3];
        }
        // convert c-frag pairs into A-frags, multiply into V
        #pragma unroll
        for (int t2 = 0; t2 < 2; t2++) {
            uint32_t af[4];
            af[0] = packbf2(lgc[2 * t2][0],     lgc[2 * t2][1]);
            af[1] = packbf2(lgc[2 * t2][2],     lgc[2 * t2][3]);
            af[2] = packbf2(lgc[2 * t2 + 1][0], lgc[2 * t2 + 1][1]);
            af[3] = packbf2(lgc[2 * t2 + 1][2], lgc[2 * t2 + 1][3]);
            int k0 = cc * 32 + t2 * 16;
            #pragma unroll
            for (int jv = 0; jv < 4; jv++) {
                uint32_t bv[4];
                ldsm_x4_t(bv, vs_b + ((k0 + fa_row) * 72 + jv * 16 + fa_col) * 2);
                mma_bf16(acc[jv * 2],     af, bv[0], bv[1]);
                mma_bf16(acc[jv * 2 + 1], af, bv[2], bv[3]);
            }
        }
    }

    // ---- normalize + store ----
    sumA += __shfl_xor_sync(0xffffffffu, sumA, 1);
    sumA += __shfl_xor_sync(0xffffffffu, sumA, 2);
    sumB += __shfl_xor_sync(0xffffffffu, sumB, 1);
    sumB += __shfl_xor_sync(0xffffffffu, sumB, 2);
    float invA = 1.f / sumA, invB = 1.f / sumB;

    __nv_bfloat16* ab = g_aob + (size_t)b * HW_ * C_ + g * HD_;
    #pragma unroll
    for (int jn = 0; jn < 8; jn++) {
        int c = jn * 8 + cc0;
        *(__nv_bfloat162*)(ab + (size_t)(pbase + r0) * C_ + c) =
            __floats2bfloat162_rn(acc[jn][0] * invA, acc[jn][1] * invA);
        *(__nv_bfloat162*)(ab + (size_t)(pbase + r0 + 8) * C_ + c) =
            __floats2bfloat162_rn(acc[jn][2] * invB, acc[jn][3] * invB);
    }
}

// ================= launch =================
extern "C" void kernel_launch(void* const* d_in, const int* in_sizes, int n_in,
                              void* d_out, int out_size) {
    const float* x   = (const float*)d_in[0];
    const float* ctx = (const float*)d_in[1];
    const float* wq  = (const float*)d_in[2];
    const float* wk  = (const float*)d_in[3];
    const float* wd  = (const float*)d_in[4];
    const float* pw  = (const float*)d_in[5];
    const float* pb  = (const float*)d_in[6];
    float* out = (float*)d_out;

    cudaFuncSetAttribute(mega2_kernel, cudaFuncAttributeMaxDynamicSharedMemorySize,
                         MG_SMEM);
    cudaFuncSetAttribute(mma_q_kernel, cudaFuncAttributeMaxDynamicSharedMemorySize,
                         Q_SMEM_BYTES);
    cudaFuncSetAttribute(mma_proj_kernel, cudaFuncAttributeMaxDynamicSharedMemorySize,
                         P_SMEM_BYTES);

    int nx4 = (B_ * C_ * HW_) / 4;
    int nw4 = (C_ * C_) / 4;
    conv_x_kernel<<<(nx4 + 255) / 256, 256>>>((const float4*)x);
    conv_w_kernel<<<(nw4 + 255) / 256, 256>>>((const float4*)wq, (const float4*)pw);

    pool_ctx_kernel<<<(B_ * CC_ * S2_ + 7) / 8, 256>>>(ctx);
    pool_v_kernel<<<(B_ * C_ * K2_ + 255) / 256, 256>>>(x);
    k_proj_kernel<<<B_ * C_, 64>>>(wk);

    mma_q_kernel<<<dim3(HW_ / 256, C_ / 128, B_), 256, Q_SMEM_BYTES>>>();
    mega2_kernel<<<dim3(HW_ / 256, B_ * G_), 512, MG_SMEM>>>(wd);
    mma_proj_kernel<<<dim3(HW_ / 256, C_ / 128, B_), 256, P_SMEM_BYTES>>>(pb, x, out);
}

// round 6
// speedup vs baseline: 4.2421x; 1.0095x over previous
#include <cuda_runtime.h>
#include <cuda_bf16.h>
#include <cstdint>
#include <math.h>

// ---------------- problem constants ----------------
#define B_   2
#define C_   768
#define CC_  384
#define G_   12
#define HD_  64
#define H_   112
#define W_   112
#define HW_  12544
#define S2_  49
#define K2_  256
#define SCALE_ 0.125f   // hd^-0.5 = 1/8, folded into k

// ---------------- static device scratch ----------------
__device__ float g_ctxp[B_ * CC_ * S2_];          // pooled ctx  (b,c,s)
__device__ float g_k   [B_ * G_ * S2_ * HD_];     // k, pre-scaled, (bg, s, c)
__device__ float g_v   [B_ * G_ * K2_ * HD_];     // v           (bg, m, c)
__device__ __nv_bfloat16 g_qb [B_ * HW_ * C_];    // q bf16       (b, p, o)
__device__ __nv_bfloat16 g_xb [B_ * C_ * HW_];    // x in bf16    (b, c, p)
__device__ __nv_bfloat16 g_wqb[C_ * C_];          // wq bf16      (o, c)
__device__ __nv_bfloat16 g_pwb[C_ * C_];          // proj_w bf16  (o, c)
__device__ __nv_bfloat16 g_aob[B_ * HW_ * C_];    // attn out bf16 (b, p, c)

// ================= fp32 -> bf16 conversions =================
__global__ void conv_x_kernel(const float4* __restrict__ src) {
    int i = blockIdx.x * blockDim.x + threadIdx.x;
    int n4 = (B_ * C_ * HW_) / 4;
    if (i >= n4) return;
    float4 v = src[i];
    __nv_bfloat162* dst = (__nv_bfloat162*)g_xb;
    dst[2 * i]     = __floats2bfloat162_rn(v.x, v.y);
    dst[2 * i + 1] = __floats2bfloat162_rn(v.z, v.w);
}

__global__ void conv_w_kernel(const float4* __restrict__ wq,
                              const float4* __restrict__ pw) {
    int i = blockIdx.x * blockDim.x + threadIdx.x;
    int n4 = (C_ * C_) / 4;
    if (i >= n4) return;
    float4 v = wq[i];
    __nv_bfloat162* dq = (__nv_bfloat162*)g_wqb;
    dq[2 * i]     = __floats2bfloat162_rn(v.x, v.y);
    dq[2 * i + 1] = __floats2bfloat162_rn(v.z, v.w);
    float4 u = pw[i];
    __nv_bfloat162* dp = (__nv_bfloat162*)g_pwb;
    dp[2 * i]     = __floats2bfloat162_rn(u.x, u.y);
    dp[2 * i + 1] = __floats2bfloat162_rn(u.z, u.w);
}

// ================= pool ctx to 7x7 (16x16 windows) =================
__global__ void pool_ctx_kernel(const float* __restrict__ ctx) {
    int warp = (blockIdx.x * blockDim.x + threadIdx.x) >> 5;
    int lane = threadIdx.x & 31;
    if (warp >= B_ * CC_ * S2_) return;
    int s  = warp % S2_;
    int bc = warp / S2_;
    int si = s / 7, sj = s % 7;
    const float* base = ctx + (size_t)bc * HW_ + (si * 16) * W_ + sj * 16;
    float sum = 0.f;
    #pragma unroll
    for (int t = lane; t < 256; t += 32)
        sum += base[(t >> 4) * W_ + (t & 15)];
    #pragma unroll
    for (int o = 16; o; o >>= 1) sum += __shfl_xor_sync(0xffffffffu, sum, o);
    if (lane == 0) g_ctxp[warp] = sum * (1.f / 256.f);
}

// ================= pool bf16 x to 16x16 (7x7 windows) -> v =================
__global__ void pool_v_kernel() {
    int idx = blockIdx.x * blockDim.x + threadIdx.x;
    if (idx >= B_ * C_ * K2_) return;
    int m  = idx % K2_;
    int bc = idx / K2_;
    int b  = bc / C_;
    int cg = bc % C_;
    int mi = m >> 4, mj = m & 15;
    const __nv_bfloat16* base = g_xb + (size_t)bc * HW_ + (mi * 7) * W_ + mj * 7;
    float sum = 0.f;
    #pragma unroll
    for (int r = 0; r < 7; r++)
        #pragma unroll
        for (int cc = 0; cc < 7; cc++)
            sum += __bfloat162float(base[r * W_ + cc]);
    int g = cg >> 6, cl = cg & 63;
    g_v[(((size_t)(b * G_ + g)) * K2_ + m) * HD_ + cl] = sum * (1.f / 49.f);
}

// ================= k = scale * wk @ pooled_ctx =================
__global__ void k_proj_kernel(const float* __restrict__ wk) {
    int bo = blockIdx.x;
    int b = bo / C_, o = bo % C_;
    int s = threadIdx.x;
    if (s >= S2_) return;
    const float* cp = g_ctxp + (size_t)b * CC_ * S2_ + s;
    const float* wr = wk + (size_t)o * CC_;
    float acc = 0.f;
    #pragma unroll 4
    for (int c = 0; c < CC_; c++) acc += wr[c] * cp[c * S2_];
    int g = o >> 6, lo = o & 63;
    g_k[(((size_t)(b * G_ + g)) * S2_ + s) * HD_ + lo] = acc * SCALE_;
}

// ================= mma.sync / cp.async helpers =================
__device__ __forceinline__ void ldsm_x4(uint32_t* r, uint32_t addr) {
    asm volatile("ldmatrix.sync.aligned.m8n8.x4.shared.b16 {%0,%1,%2,%3}, [%4];"
        : "=r"(r[0]), "=r"(r[1]), "=r"(r[2]), "=r"(r[3]) : "r"(addr));
}
__device__ __forceinline__ void ldsm_x4_t(uint32_t* r, uint32_t addr) {
    asm volatile("ldmatrix.sync.aligned.m8n8.x4.trans.shared.b16 {%0,%1,%2,%3}, [%4];"
        : "=r"(r[0]), "=r"(r[1]), "=r"(r[2]), "=r"(r[3]) : "r"(addr));
}
__device__ __forceinline__ void mma_bf16(float* c, const uint32_t* a,
                                         uint32_t b0, uint32_t b1) {
    asm volatile("mma.sync.aligned.m16n8k16.row.col.f32.bf16.bf16.f32 "
        "{%0,%1,%2,%3}, {%4,%5,%6,%7}, {%8,%9}, {%0,%1,%2,%3};"
        : "+f"(c[0]), "+f"(c[1]), "+f"(c[2]), "+f"(c[3])
        : "r"(a[0]), "r"(a[1]), "r"(a[2]), "r"(a[3]), "r"(b0), "r"(b1));
}
__device__ __forceinline__ uint32_t packbf2(float x, float y) {
    __nv_bfloat162 t = __floats2bfloat162_rn(x, y);
    return *(uint32_t*)&t;
}
__device__ __forceinline__ void cp16(uint32_t dst, const void* src) {
    asm volatile("cp.async.cg.shared.global [%0], [%1], 16;" :: "r"(dst), "l"(src));
}
__device__ __forceinline__ void cp_commit() {
    asm volatile("cp.async.commit_group;");
}
__device__ __forceinline__ void cp_wait1() {
    asm volatile("cp.async.wait_group 1;");
}

// tiles: A(q) [k=32][m=256] pad 264 | A(proj) [m=256][k=32] pad 40 | B [n=128][k=32] pad 40
#define Q_ASZ (32 * 264)
#define P_ASZ (256 * 40)
#define MM_BSZ (128 * 40)
#define NSTAGE 3
#define Q_SMEM_BYTES ((NSTAGE * Q_ASZ + NSTAGE * MM_BSZ) * 2)
#define P_SMEM_BYTES ((NSTAGE * P_ASZ + NSTAGE * MM_BSZ) * 2)

// ================= GEMM-q: g_qb[b,p,o] = sum_c xb[b,c,p] * wqb[o,c] (bf16 out) =================
__global__ __launch_bounds__(256) void mma_q_kernel() {
    extern __shared__ __align__(16) __nv_bfloat16 smq[];
    __nv_bfloat16* As = smq;                        // NSTAGE x 32 x 264
    __nv_bfloat16* Bs = smq + NSTAGE * Q_ASZ;       // NSTAGE x 128 x 40

    int b  = blockIdx.z;
    int p0 = blockIdx.x * 256, o0 = blockIdx.y * 128;
    const __nv_bfloat16* A  = g_xb + (size_t)b * C_ * HW_;
    const __nv_bfloat16* Bm = g_wqb;

    int tid = threadIdx.x, lane = tid & 31, w = tid >> 5;
    int wm = (w & 3) * 64, wn = (w >> 2) * 64;

    int a_k = tid >> 5, a_m = (tid & 31) * 8;
    int b_n = tid >> 2, b_k = (tid & 3) * 8;

    uint32_t as_base = (uint32_t)__cvta_generic_to_shared(As);
    uint32_t bs_base = (uint32_t)__cvta_generic_to_shared(Bs);

    // per-thread load: 4 A cp16 + 2 B cp16 per stage
    auto load_tile = [&](int stage, int kc0) {
        uint32_t ad = as_base + stage * (Q_ASZ * 2);
        uint32_t bd = bs_base + stage * (MM_BSZ * 2);
        #pragma unroll
        for (int i = 0; i < 4; i++)
            cp16(ad + ((a_k + i * 8) * 264 + a_m) * 2,
                 A + (size_t)(kc0 + a_k + i * 8) * HW_ + p0 + a_m);
        #pragma unroll
        for (int i = 0; i < 2; i++)
            cp16(bd + ((b_n + i * 64) * 40 + b_k) * 2,
                 Bm + (size_t)(o0 + b_n + i * 64) * C_ + kc0 + b_k);
    };

    int lr = lane & 7, lg = lane >> 3;
    int at_row = ((lg >> 1) << 3) + lr, at_col = (lg & 1) << 3;
    int bt_row = ((lg >> 1) << 3) + lr, bt_col = (lg & 1) << 3;

    float acc[4][8][4];
    #pragma unroll
    for (int i = 0; i < 4; i++)
        #pragma unroll
        for (int j = 0; j < 8; j++)
            #pragma unroll
            for (int t = 0; t < 4; t++) acc[i][j][t] = 0.f;

    load_tile(0, 0);  cp_commit();
    load_tile(1, 32); cp_commit();
    cp_wait1();
    __syncthreads();   // stage 0 ready & visible

    for (int kc = 0; kc < 24; kc++) {
        // issue stage kc+2 into buffer (kc+2)%3 (consumed at iteration kc-1)
        if (kc + 2 < 24) load_tile((kc + 2) % NSTAGE, (kc + 2) * 32);
        cp_commit();   // (possibly empty group — keeps counting uniform)

        int cur = kc % NSTAGE;
        uint32_t asb = as_base + cur * (Q_ASZ * 2);
        uint32_t bsb = bs_base + cur * (MM_BSZ * 2);
        #pragma unroll
        for (int kk = 0; kk < 32; kk += 16) {
            uint32_t af[4][4], bf[4][4];
            #pragma unroll
            for (int i = 0; i < 4; i++)
                ldsm_x4_t(af[i], asb + ((kk + at_row) * 264 + wm + i * 16 + at_col) * 2);
            #pragma unroll
            for (int j2 = 0; j2 < 4; j2++)
                ldsm_x4(bf[j2], bsb + ((wn + j2 * 16 + bt_row) * 40 + kk + bt_col) * 2);
            #pragma unroll
            for (int i = 0; i < 4; i++)
                #pragma unroll
                for (int j = 0; j < 8; j++)
                    mma_bf16(acc[i][j], af[i], bf[j >> 1][(j & 1) * 2], bf[j >> 1][(j & 1) * 2 + 1]);
        }
        cp_wait1();       // stage kc+1 complete (this thread)
        __syncthreads();  // all threads' copies visible
    }

    __nv_bfloat16* outp = g_qb + (size_t)b * HW_ * C_;
    int rr = lane >> 2, cc0 = (lane & 3) * 2;
    #pragma unroll
    for (int i = 0; i < 4; i++)
        #pragma unroll
        for (int j = 0; j < 8; j++) {
            int r0 = p0 + wm + i * 16 + rr;
            int cc = o0 + wn + j * 8 + cc0;
            *(__nv_bfloat162*)(outp + (size_t)r0 * C_ + cc) =
                __floats2bfloat162_rn(acc[i][j][0], acc[i][j][1]);
            *(__nv_bfloat162*)(outp + (size_t)(r0 + 8) * C_ + cc) =
                __floats2bfloat162_rn(acc[i][j][2], acc[i][j][3]);
        }
}

// ================= GEMM-proj: out = aob @ pw^T + pb + x =================
__global__ __launch_bounds__(256) void mma_proj_kernel(const float* __restrict__ pbias,
                                                       const float* __restrict__ x,
                                                       float* __restrict__ out) {
    extern __shared__ __align__(16) __nv_bfloat16 smp[];
    __nv_bfloat16* As = smp;                        // NSTAGE x 256 x 40
    __nv_bfloat16* Bs = smp + NSTAGE * P_ASZ;       // NSTAGE x 128 x 40

    int b  = blockIdx.z;
    int p0 = blockIdx.x * 256, o0 = blockIdx.y * 128;
    const __nv_bfloat16* A  = g_aob + (size_t)b * HW_ * C_;
    const __nv_bfloat16* Bm = g_pwb;

    int tid = threadIdx.x, lane = tid & 31, w = tid >> 5;
    int wm = (w & 3) * 64, wn = (w >> 2) * 64;

    int a_m = tid >> 2, a_kq = (tid & 3) * 8;
    int b_n = tid >> 2, b_k = (tid & 3) * 8;

    uint32_t as_base = (uint32_t)__cvta_generic_to_shared(As);
    uint32_t bs_base = (uint32_t)__cvta_generic_to_shared(Bs);

    auto load_tile = [&](int stage, int kc0) {
        uint32_t ad = as_base + stage * (P_ASZ * 2);
        uint32_t bd = bs_base + stage * (MM_BSZ * 2);
        #pragma unroll
        for (int i = 0; i < 4; i++)
            cp16(ad + ((a_m + i * 64) * 40 + a_kq) * 2,
                 A + (size_t)(p0 + a_m + i * 64) * C_ + kc0 + a_kq);
        #pragma unroll
        for (int i = 0; i < 2; i++)
            cp16(bd + ((b_n + i * 64) * 40 + b_k) * 2,
                 Bm + (size_t)(o0 + b_n + i * 64) * C_ + kc0 + b_k);
    };

    int lr = lane & 7, lg = lane >> 3;
    int an_row = ((lg & 1) << 3) + lr, an_col = (lg >> 1) << 3;
    int bt_row = ((lg >> 1) << 3) + lr, bt_col = (lg & 1) << 3;

    float acc[4][8][4];
    #pragma unroll
    for (int i = 0; i < 4; i++)
        #pragma unroll
        for (int j = 0; j < 8; j++)
            #pragma unroll
            for (int t = 0; t < 4; t++) acc[i][j][t] = 0.f;

    load_tile(0, 0);  cp_commit();
    load_tile(1, 32); cp_commit();
    cp_wait1();
    __syncthreads();

    for (int kc = 0; kc < 24; kc++) {
        if (kc + 2 < 24) load_tile((kc + 2) % NSTAGE, (kc + 2) * 32);
        cp_commit();

        int cur = kc % NSTAGE;
        uint32_t asb = as_base + cur * (P_ASZ * 2);
        uint32_t bsb = bs_base + cur * (MM_BSZ * 2);
        #pragma unroll
        for (int kk = 0; kk < 32; kk += 16) {
            uint32_t af[4][4], bf[4][4];
            #pragma unroll
            for (int i = 0; i < 4; i++)
                ldsm_x4(af[i], asb + ((wm + i * 16 + an_row) * 40 + kk + an_col) * 2);
            #pragma unroll
            for (int j2 = 0; j2 < 4; j2++)
                ldsm_x4(bf[j2], bsb + ((wn + j2 * 16 + bt_row) * 40 + kk + bt_col) * 2);
            #pragma unroll
            for (int i = 0; i < 4; i++)
                #pragma unroll
                for (int j = 0; j < 8; j++)
                    mma_bf16(acc[i][j], af[i], bf[j >> 1][(j & 1) * 2], bf[j >> 1][(j & 1) * 2 + 1]);
        }
        cp_wait1();
        __syncthreads();
    }

    int rr = lane >> 2, cc0 = (lane & 3) * 2;
    #pragma unroll
    for (int i = 0; i < 4; i++)
        #pragma unroll
        for (int j = 0; j < 8; j++) {
            int p = p0 + wm + i * 16 + rr;
            int o = o0 + wn + j * 8 + cc0;
            float b0 = pbias[o], b1 = pbias[o + 1];
            size_t base0 = ((size_t)(b * C_ + o)) * HW_;
            size_t base1 = base0 + HW_;
            out[base0 + p]     = acc[i][j][0] + b0 + x[base0 + p];
            out[base1 + p]     = acc[i][j][1] + b1 + x[base1 + p];
            out[base0 + p + 8] = acc[i][j][2] + b0 + x[base0 + p + 8];
            out[base1 + p + 8] = acc[i][j][3] + b1 + x[base1 + p + 8];
        }
}

// ================= mega2: tensor-core attn -> top32 -> logits -> softmax -> @V =================
#define MG_WD   0
#define MG_V    36864
#define MG_K    73728
#define MG_WB   82944
#define MG_SMEM (82944 + 16 * 8192)   // 214016

__global__ __launch_bounds__(512) void mega2_kernel(const float* __restrict__ wd) {
    extern __shared__ __align__(16) char smraw[];
    __nv_bfloat16* wds = (__nv_bfloat16*)(smraw + MG_WD);
    __nv_bfloat16* vs  = (__nv_bfloat16*)(smraw + MG_V);
    __nv_bfloat16* ks  = (__nv_bfloat16*)(smraw + MG_K);
    int tid = threadIdx.x, lane = tid & 31, w = tid >> 5;
    char* wb = smraw + MG_WB + w * 8192;
    __nv_bfloat16* qs = (__nv_bfloat16*)wb;
    __nv_bfloat16* sp = (__nv_bfloat16*)(wb + 2304);
    float* att = (float*)(wb + 4608);

    int bg = blockIdx.y;
    int b = bg / G_, g = bg % G_;
    __nv_bfloat16 zero = __float2bfloat16(0.f);

    for (int i = tid; i < K2_ * 64; i += 512) {
        int r = i >> 6, c = i & 63;
        wds[r * 72 + c] = (c < S2_) ? __float2bfloat16(wd[r * S2_ + c]) : zero;
        vs[r * 72 + c]  = __float2bfloat16(g_v[(size_t)bg * K2_ * HD_ + i]);
    }
    for (int i = tid; i < 64 * 64; i += 512) {
        int r = i >> 6, c = i & 63;
        ks[r * 72 + c] = (r < S2_) ? __float2bfloat16(g_k[(size_t)bg * S2_ * HD_ + r * HD_ + c]) : zero;
    }
    __syncthreads();

    int pbase = blockIdx.x * 256 + w * 16;
    const __nv_bfloat16* qb = g_qb + (size_t)b * HW_ * C_ + g * HD_;

    for (int i = lane; i < 128; i += 32) {
        int r = i >> 3, cq = (i & 7) * 8;
        *(uint4*)(qs + r * 72 + cq) = *(const uint4*)(qb + (size_t)(pbase + r) * C_ + cq);
    }
    __syncwarp();

    int lr = lane & 7, lg = lane >> 3;
    int fa_row = ((lg & 1) << 3) + lr, fa_col = (lg >> 1) << 3;
    int fb_row = ((lg >> 1) << 3) + lr, fb_col = (lg & 1) << 3;
    uint32_t qs_b = (uint32_t)__cvta_generic_to_shared(qs);
    uint32_t sp_b = (uint32_t)__cvta_generic_to_shared(sp);
    uint32_t ks_b = (uint32_t)__cvta_generic_to_shared(ks);
    uint32_t wd_b = (uint32_t)__cvta_generic_to_shared(wds);
    uint32_t vs_b = (uint32_t)__cvta_generic_to_shared(vs);

    // ---- attn = q @ k^T ----
    uint32_t aq[4][4];
    #pragma unroll
    for (int kt = 0; kt < 4; kt++)
        ldsm_x4(aq[kt], qs_b + (fa_row * 72 + kt * 16 + fa_col) * 2);
    float ac[8][4];
    #pragma unroll
    for (int j = 0; j < 8; j++)
        #pragma unroll
        for (int t = 0; t < 4; t++) ac[j][t] = 0.f;
    #pragma unroll
    for (int kt = 0; kt < 4; kt++)
        #pragma unroll
        for (int jp = 0; jp < 4; jp++) {
            uint32_t bk[4];
            ldsm_x4(bk, ks_b + ((jp * 16 + fb_row) * 72 + kt * 16 + fb_col) * 2);
            mma_bf16(ac[jp * 2],     aq[kt], bk[0], bk[1]);
            mma_bf16(ac[jp * 2 + 1], aq[kt], bk[2], bk[3]);
        }

    int r0 = lane >> 2, cc0 = (lane & 3) * 2;
    #pragma unroll
    for (int jn = 0; jn < 7; jn++) {
        int col = jn * 8 + cc0;
        if (col < 52) {
            att[r0 * 52 + col]       = ac[jn][0];
            att[(r0 + 8) * 52 + col] = ac[jn][2];
        }
        if (col + 1 < 52) {
            att[r0 * 52 + col + 1]       = ac[jn][1];
            att[(r0 + 8) * 52 + col + 1] = ac[jn][3];
        }
    }
    __syncwarp();

    // ---- top-32 threshold per row ----
    int s1 = lane, s2 = lane + 32;
    for (int r = 0; r < 16; r++) {
        float a1 = att[r * 52 + s1];
        float a2 = (s2 < S2_) ? att[r * 52 + s2] : 0.f;
        int c1 = 0, c2 = 0;
        #pragma unroll
        for (int j = 0; j < S2_; j++) {
            float v = att[r * 52 + j];
            c1 += (v > a1);
            c2 += (v > a2);
        }
        __syncwarp();
        if (c1 >= 32) att[r * 52 + s1] = 0.f;
        if (s2 < S2_ && c2 >= 32) att[r * 52 + s2] = 0.f;
    }
    __syncwarp();

    // ---- stage sparse as bf16 16x64 ----
    for (int i = lane; i < 256; i += 32) {
        int r = i >> 4, c = 48 + (i & 15);
        sp[r * 72 + c] = zero;
    }
    __syncwarp();
    for (int r = 0; r < 16; r++) {
        sp[r * 72 + s1] = __float2bfloat16(att[r * 52 + s1]);
        if (s2 < S2_) sp[r * 72 + s2] = __float2bfloat16(att[r * 52 + s2]);
    }
    __syncwarp();

    uint32_t asp[4][4];
    #pragma unroll
    for (int kt = 0; kt < 4; kt++)
        ldsm_x4(asp[kt], sp_b + (fa_row * 72 + kt * 16 + fa_col) * 2);

    // ---- chunked: logits -> exp -> omega @ V ----
    float acc[8][4];
    #pragma unroll
    for (int j = 0; j < 8; j++)
        #pragma unroll
        for (int t = 0; t < 4; t++) acc[j][t] = 0.f;
    float sumA = 0.f, sumB = 0.f;

    for (int cc = 0; cc < 8; cc++) {
        float lgc[4][4];
        #pragma unroll
        for (int t = 0; t < 4; t++)
            #pragma unroll
            for (int u = 0; u < 4; u++) lgc[t][u] = 0.f;
        #pragma unroll
        for (int kt = 0; kt < 4; kt++)
            #pragma unroll
            for (int jp = 0; jp < 2; jp++) {
                uint32_t bw[4];
                ldsm_x4(bw, wd_b + ((cc * 32 + jp * 16 + fb_row) * 72 + kt * 16 + fb_col) * 2);
                mma_bf16(lgc[jp * 2],     asp[kt], bw[0], bw[1]);
                mma_bf16(lgc[jp * 2 + 1], asp[kt], bw[2], bw[3]);
            }
        #pragma unroll
        for (int t = 0; t < 4; t++) {
            #pragma unroll
            for (int u = 0; u < 4; u++) lgc[t][u] = __expf(lgc[t][u]);
            sumA += lgc[t][0] + lgc[t][1];
            sumB += lgc[t][2] + lgc[t][3];
        }
        #pragma unroll
        for (int t2 = 0; t2 < 2; t2++) {
            uint32_t af[4];
            af[0] = packbf2(lgc[2 * t2][0],     lgc[2 * t2][1]);
            af[1] = packbf2(lgc[2 * t2][2],     lgc[2 * t2][3]);
            af[2] = packbf2(lgc[2 * t2 + 1][0], lgc[2 * t2 + 1][1]);
            af[3] = packbf2(lgc[2 * t2 + 1][2], lgc[2 * t2 + 1][3]);
            int k0 = cc * 32 + t2 * 16;
            #pragma unroll
            for (int jv = 0; jv < 4; jv++) {
                uint32_t bv[4];
                ldsm_x4_t(bv, vs_b + ((k0 + fa_row) * 72 + jv * 16 + fa_col) * 2);
                mma_bf16(acc[jv * 2],     af, bv[0], bv[1]);
                mma_bf16(acc[jv * 2 + 1], af, bv[2], bv[3]);
            }
        }
    }

    sumA += __shfl_xor_sync(0xffffffffu, sumA, 1);
    sumA += __shfl_xor_sync(0xffffffffu, sumA, 2);
    sumB += __shfl_xor_sync(0xffffffffu, sumB, 1);
    sumB += __shfl_xor_sync(0xffffffffu, sumB, 2);
    float invA = 1.f / sumA, invB = 1.f / sumB;

    __nv_bfloat16* ab = g_aob + (size_t)b * HW_ * C_ + g * HD_;
    #pragma unroll
    for (int jn = 0; jn < 8; jn++) {
        int c = jn * 8 + cc0;
        *(__nv_bfloat162*)(ab + (size_t)(pbase + r0) * C_ + c) =
            __floats2bfloat162_rn(acc[jn][0] * invA, acc[jn][1] * invA);
        *(__nv_bfloat162*)(ab + (size_t)(pbase + r0 + 8) * C_ + c) =
            __floats2bfloat162_rn(acc[jn][2] * invB, acc[jn][3] * invB);
    }
}

// ================= launch =================
extern "C" void kernel_launch(void* const* d_in, const int* in_sizes, int n_in,
                              void* d_out, int out_size) {
    const float* x   = (const float*)d_in[0];
    const float* ctx = (const float*)d_in[1];
    const float* wq  = (const float*)d_in[2];
    const float* wk  = (const float*)d_in[3];
    const float* wd  = (const float*)d_in[4];
    const float* pw  = (const float*)d_in[5];
    const float* pb  = (const float*)d_in[6];
    float* out = (float*)d_out;

    cudaFuncSetAttribute(mega2_kernel, cudaFuncAttributeMaxDynamicSharedMemorySize,
                         MG_SMEM);
    cudaFuncSetAttribute(mma_q_kernel, cudaFuncAttributeMaxDynamicSharedMemorySize,
                         Q_SMEM_BYTES);
    cudaFuncSetAttribute(mma_proj_kernel, cudaFuncAttributeMaxDynamicSharedMemorySize,
                         P_SMEM_BYTES);

    int nx4 = (B_ * C_ * HW_) / 4;
    int nw4 = (C_ * C_) / 4;
    conv_x_kernel<<<(nx4 + 255) / 256, 256>>>((const float4*)x);
    conv_w_kernel<<<(nw4 + 255) / 256, 256>>>((const float4*)wq, (const float4*)pw);

    pool_ctx_kernel<<<(B_ * CC_ * S2_ + 7) / 8, 256>>>(ctx);
    pool_v_kernel<<<(B_ * C_ * K2_ + 255) / 256, 256>>>();
    k_proj_kernel<<<B_ * C_, 64>>>(wk);

    mma_q_kernel<<<dim3(HW_ / 256, C_ / 128, B_), 256, Q_SMEM_BYTES>>>();
    mega2_kernel<<<dim3(HW_ / 256, B_ * G_), 512, MG_SMEM>>>(wd);
    mma_proj_kernel<<<dim3(HW_ / 256, C_ / 128, B_), 256, P_SMEM_BYTES>>>(pb, x, out);
}